// round 16
// baseline (speedup 1.0000x reference)
#include <cuda_runtime.h>
#include <cuda_fp16.h>
#include <cstdint>
#include <math.h>

#define E_ 8
#define C_ 1024
#define H_ 2048
#define I_ 5632

__device__ __half x16[(size_t)E_ * C_ * H_];
__device__ __half g16[(size_t)E_ * I_ * H_];
__device__ __half u16[(size_t)E_ * I_ * H_];
__device__ __half d16[(size_t)E_ * H_ * I_];
__device__ __half inter16[(size_t)E_ * C_ * I_];
__device__ __half gateh[(size_t)E_ * C_ * I_];

constexpr int BM = 128, BN = 128, BK = 32;   // elements
constexpr int LDSH = 40;                     // halves; 80B rows, conflict-free
constexpr int STAGE_H = (BM + BN) * LDSH;    // 10240 halves = 20480 B
constexpr int SMEM_BYTES = 2 * STAGE_H * 2;  // 40960 B -> 3 CTAs/SM
constexpr int THREADS = 128;                 // 2x2 warps, warp tile 64x64

__device__ __forceinline__ void mma_f16(float (&c)[4], const uint32_t (&a)[4],
                                        uint32_t b0, uint32_t b1) {
    asm volatile(
        "mma.sync.aligned.m16n8k16.row.col.f32.f16.f16.f32 "
        "{%0,%1,%2,%3}, {%4,%5,%6,%7}, {%8,%9}, {%0,%1,%2,%3};\n"
        : "+f"(c[0]), "+f"(c[1]), "+f"(c[2]), "+f"(c[3])
        : "r"(a[0]), "r"(a[1]), "r"(a[2]), "r"(a[3]), "r"(b0), "r"(b1));
}
__device__ __forceinline__ void ldsm_x4(uint32_t (&r)[4], uint32_t addr) {
    asm volatile("ldmatrix.sync.aligned.m8n8.x4.shared.b16 {%0,%1,%2,%3}, [%4];"
                 : "=r"(r[0]), "=r"(r[1]), "=r"(r[2]), "=r"(r[3]) : "r"(addr));
}
__device__ __forceinline__ void cp_async16(void* smem_ptr, const void* gmem_ptr) {
    uint32_t s = (uint32_t)__cvta_generic_to_shared(smem_ptr);
    asm volatile("cp.async.cg.shared.global [%0], [%1], 16;\n" ::"r"(s), "l"(gmem_ptr));
}
__device__ __forceinline__ void cp_commit() { asm volatile("cp.async.commit_group;\n"); }
template <int N>
__device__ __forceinline__ void cp_wait() {
    asm volatile("cp.async.wait_group %0;\n" ::"n"(N));
}
__device__ __forceinline__ float silu(float x) { return x / (1.f + __expf(-x)); }

__global__ void f2h(const float4* __restrict__ src, uint2* __restrict__ dst, size_t n4) {
    size_t i = (size_t)blockIdx.x * blockDim.x + threadIdx.x;
    const size_t stride = (size_t)gridDim.x * blockDim.x;
    for (; i < n4; i += stride) {
        float4 v = src[i];
        __half2 h0 = __floats2half2_rn(v.x, v.y);
        __half2 h1 = __floats2half2_rn(v.z, v.w);
        dst[i] = make_uint2(*reinterpret_cast<uint32_t*>(&h0), *reinterpret_cast<uint32_t*>(&h1));
    }
}

// C[e,m,n] = sum_k A[e,m,k]*B[e,n,k]; fp16 in, fp32 acc. (e = blockIdx.z)
// MODE 0: raw acc -> __half*; MODE 1: silu(Gpre)*acc -> __half*; MODE 2: raw acc -> float*
template <int MODE>
__global__ void __launch_bounds__(THREADS, 3)
gemm_nt(const __half* __restrict__ A, const __half* __restrict__ B,
        const __half* __restrict__ Gpre, void* __restrict__ CoutV,
        int N, int K, long strideA, long strideB, long strideC) {
    extern __shared__ __half smh[];
    const uint32_t smbase = (uint32_t)__cvta_generic_to_shared(smh);

    const int e = blockIdx.z;
    const __half* Ae = A + (long)e * strideA;
    const __half* Be = B + (long)e * strideB;

    const int bm = blockIdx.y, bn = blockIdx.x;
    const int tid = threadIdx.x;
    const int warp = tid >> 5, lane = tid & 31;
    const int wm = warp >> 1, wn = warp & 1;
    const int gid = lane >> 2, tig = lane & 3;

    const uint32_t aoff = ((uint32_t)(((lane & 7) + ((lane >> 3) & 1) * 8) * LDSH +
                                      ((lane >> 4) & 1) * 8)) * 2;
    const uint32_t boff = ((uint32_t)(((lane & 7) + ((lane >> 4) & 1) * 8) * LDSH +
                                      ((lane >> 3) & 1) * 8)) * 2;

    const int lrow = tid >> 2;
    const int lch = (tid & 3) * 8;

    const __half* Ag = Ae + (long)(bm * BM + lrow) * K + lch;
    const __half* Bg = Be + (long)(bn * BN + lrow) * K + lch;

    float acc[4][8][4];
#pragma unroll
    for (int mt = 0; mt < 4; mt++)
#pragma unroll
        for (int nt = 0; nt < 8; nt++)
#pragma unroll
            for (int r = 0; r < 4; r++) acc[mt][nt][r] = 0.f;

    const int KT = K / BK;

    auto load_stage = [&](int kt) {
        __half* as = smh + (kt & 1) * STAGE_H;
        __half* bs = as + BM * LDSH;
        const long ko = (long)kt * BK;
#pragma unroll
        for (int i = 0; i < 4; i++) {
            cp_async16(&as[(lrow + i * 32) * LDSH + lch], Ag + (long)(i * 32) * K + ko);
            cp_async16(&bs[(lrow + i * 32) * LDSH + lch], Bg + (long)(i * 32) * K + ko);
        }
    };

    load_stage(0); cp_commit();

    for (int kt = 0; kt < KT; ++kt) {
        if (kt + 1 < KT) load_stage(kt + 1);
        cp_commit();
        cp_wait<1>();
        __syncthreads();

        const uint32_t as_u = smbase + (uint32_t)((kt & 1) * STAGE_H * 2);
        const uint32_t abase = as_u + (uint32_t)(wm * 64 * LDSH * 2) + aoff;
        const uint32_t bbase = as_u + (uint32_t)(BM * LDSH * 2) + (uint32_t)(wn * 64 * LDSH * 2) + boff;

#pragma unroll
        for (int k16 = 0; k16 < BK / 16; k16++) {
            const uint32_t kcb = (uint32_t)(k16 * 32);
            uint32_t afr[4][4];
            uint32_t bfr[4][4];
#pragma unroll
            for (int mt = 0; mt < 4; mt++)
                ldsm_x4(afr[mt], abase + (uint32_t)(mt * 16 * LDSH * 2) + kcb);
#pragma unroll
            for (int p = 0; p < 4; p++)
                ldsm_x4(bfr[p], bbase + (uint32_t)(p * 16 * LDSH * 2) + kcb);
#pragma unroll
            for (int mt = 0; mt < 4; mt++)
#pragma unroll
                for (int nt = 0; nt < 8; nt++)
                    mma_f16(acc[mt][nt], afr[mt], bfr[nt >> 1][(nt & 1) * 2],
                            bfr[nt >> 1][(nt & 1) * 2 + 1]);
        }
        __syncthreads();
    }

    const long base = (long)e * strideC;
#pragma unroll
    for (int mt = 0; mt < 4; mt++) {
#pragma unroll
        for (int nt = 0; nt < 8; nt++) {
            const int row0 = bm * BM + wm * 64 + mt * 16 + gid;
            const int col = bn * BN + wn * 64 + nt * 8 + tig * 2;
            const long i0 = base + (long)row0 * N + col;
            const long i1 = base + (long)(row0 + 8) * N + col;
            if (MODE == 0) {
                __half* Cout = (__half*)CoutV;
                *reinterpret_cast<__half2*>(Cout + i0) =
                    __floats2half2_rn(acc[mt][nt][0], acc[mt][nt][1]);
                *reinterpret_cast<__half2*>(Cout + i1) =
                    __floats2half2_rn(acc[mt][nt][2], acc[mt][nt][3]);
            } else if (MODE == 1) {
                __half* Cout = (__half*)CoutV;
                const float2 g0 = __half22float2(*reinterpret_cast<const __half2*>(Gpre + i0));
                const float2 g1 = __half22float2(*reinterpret_cast<const __half2*>(Gpre + i1));
                *reinterpret_cast<__half2*>(Cout + i0) =
                    __floats2half2_rn(silu(g0.x) * acc[mt][nt][0], silu(g0.y) * acc[mt][nt][1]);
                *reinterpret_cast<__half2*>(Cout + i1) =
                    __floats2half2_rn(silu(g1.x) * acc[mt][nt][2], silu(g1.y) * acc[mt][nt][3]);
            } else {
                float* Cout = (float*)CoutV;
                *reinterpret_cast<float2*>(Cout + i0) = make_float2(acc[mt][nt][0], acc[mt][nt][1]);
                *reinterpret_cast<float2*>(Cout + i1) = make_float2(acc[mt][nt][2], acc[mt][nt][3]);
            }
        }
    }
}

extern "C" void kernel_launch(void* const* d_in, const int* in_sizes, int n_in,
                              void* d_out, int out_size) {
    const float* x    = (const float*)d_in[0];
    const float* gate = (const float*)d_in[1];
    const float* up   = (const float*)d_in[2];
    const float* down = (const float*)d_in[3];
    float* out = (float*)d_out;

    __half *px16, *pg16, *pu16, *pd16, *pi16, *pgh;
    cudaGetSymbolAddress((void**)&px16, x16);
    cudaGetSymbolAddress((void**)&pg16, g16);
    cudaGetSymbolAddress((void**)&pu16, u16);
    cudaGetSymbolAddress((void**)&pd16, d16);
    cudaGetSymbolAddress((void**)&pi16, inter16);
    cudaGetSymbolAddress((void**)&pgh, gateh);

    cudaFuncSetAttribute(gemm_nt<0>, cudaFuncAttributeMaxDynamicSharedMemorySize, SMEM_BYTES);
    cudaFuncSetAttribute(gemm_nt<1>, cudaFuncAttributeMaxDynamicSharedMemorySize, SMEM_BYTES);
    cudaFuncSetAttribute(gemm_nt<2>, cudaFuncAttributeMaxDynamicSharedMemorySize, SMEM_BYTES);

    static cudaStream_t s2 = nullptr;   // GEMM stream
    static cudaEvent_t evg[E_], ev_up = nullptr, ev_down = nullptr, ev_join = nullptr;
    if (!s2) {
        cudaStreamCreateWithFlags(&s2, cudaStreamNonBlocking);
        for (int e = 0; e < E_; e++) cudaEventCreateWithFlags(&evg[e], cudaEventDisableTiming);
        cudaEventCreateWithFlags(&ev_up, cudaEventDisableTiming);
        cudaEventCreateWithFlags(&ev_down, cudaEventDisableTiming);
        cudaEventCreateWithFlags(&ev_join, cudaEventDisableTiming);
    }

    const size_t nX = (size_t)E_ * C_ * H_, nW = (size_t)E_ * I_ * H_, nD = (size_t)E_ * H_ * I_;
    const size_t nWe = (size_t)I_ * H_;          // per-expert weight elements
    const long sA0 = (long)C_ * H_, sB0 = (long)I_ * H_, sC0 = (long)C_ * I_;

    // conversion stream (capture stream 0): x, then gate per-expert, then up, down
    f2h<<<1024, 256>>>((const float4*)x, (uint2*)px16, nX / 4);
    for (int e = 0; e < E_; e++) {
        f2h<<<256, 256>>>((const float4*)(gate + (size_t)e * nWe),
                          (uint2*)(pg16 + (size_t)e * nWe), nWe / 4);
        cudaEventRecord(evg[e], 0);
    }
    f2h<<<2048, 256>>>((const float4*)up, (uint2*)pu16, nW / 4);
    cudaEventRecord(ev_up, 0);
    f2h<<<2048, 256>>>((const float4*)down, (uint2*)pd16, nD / 4);
    cudaEventRecord(ev_down, 0);

    dim3 blk(THREADS);

    // GEMM stream: per-expert gemm0 as soon as that expert's gate weights are ready
    for (int e = 0; e < E_; e++) {
        cudaStreamWaitEvent(s2, evg[e], 0);
        gemm_nt<0><<<dim3(I_ / BN, C_ / BM, 1), blk, SMEM_BYTES, s2>>>(
            px16 + (size_t)e * sA0, pg16 + (size_t)e * sB0, nullptr,
            pgh + (size_t)e * sC0, I_, H_, sA0, sB0, sC0);
    }

    cudaStreamWaitEvent(s2, ev_up, 0);
    gemm_nt<1><<<dim3(I_ / BN, C_ / BM, E_), blk, SMEM_BYTES, s2>>>(
        px16, pu16, pgh, pi16, I_, H_, sA0, sB0, sC0);

    cudaStreamWaitEvent(s2, ev_down, 0);
    gemm_nt<2><<<dim3(H_ / BN, C_ / BM, E_), blk, SMEM_BYTES, s2>>>(
        pi16, pd16, nullptr, out, H_, I_,
        (long)C_ * I_, (long)H_ * I_, (long)C_ * H_);

    // join result back to the capture stream
    cudaEventRecord(ev_join, s2);
    cudaStreamWaitEvent(0, ev_join, 0);
}

// round 17
// speedup vs baseline: 1.0756x; 1.0756x over previous
#include <cuda_runtime.h>
#include <cuda_fp16.h>
#include <cstdint>
#include <math.h>

#define E_ 8
#define C_ 1024
#define H_ 2048
#define I_ 5632

__device__ __half x16[(size_t)E_ * C_ * H_];
__device__ __half g16[(size_t)E_ * I_ * H_];
__device__ __half u16[(size_t)E_ * I_ * H_];
__device__ __half d16[(size_t)E_ * H_ * I_];
__device__ __half inter16[(size_t)E_ * C_ * I_];
__device__ __half gateh[(size_t)E_ * C_ * I_];

constexpr int BM = 128, BN = 128, BK = 32;   // elements
constexpr int LDSH = 40;                     // halves; 80B rows, conflict-free
constexpr int STAGE_H = (BM + BN) * LDSH;    // 10240 halves = 20480 B
constexpr int SMEM_BYTES = 2 * STAGE_H * 2;  // 40960 B -> 3 CTAs/SM
constexpr int THREADS = 128;                 // 2x2 warps, warp tile 64x64

__device__ __forceinline__ void mma_f16(float (&c)[4], const uint32_t (&a)[4],
                                        uint32_t b0, uint32_t b1) {
    asm volatile(
        "mma.sync.aligned.m16n8k16.row.col.f32.f16.f16.f32 "
        "{%0,%1,%2,%3}, {%4,%5,%6,%7}, {%8,%9}, {%0,%1,%2,%3};\n"
        : "+f"(c[0]), "+f"(c[1]), "+f"(c[2]), "+f"(c[3])
        : "r"(a[0]), "r"(a[1]), "r"(a[2]), "r"(a[3]), "r"(b0), "r"(b1));
}
__device__ __forceinline__ void ldsm_x4(uint32_t (&r)[4], uint32_t addr) {
    asm volatile("ldmatrix.sync.aligned.m8n8.x4.shared.b16 {%0,%1,%2,%3}, [%4];"
                 : "=r"(r[0]), "=r"(r[1]), "=r"(r[2]), "=r"(r[3]) : "r"(addr));
}
__device__ __forceinline__ void cp_async16(void* smem_ptr, const void* gmem_ptr) {
    uint32_t s = (uint32_t)__cvta_generic_to_shared(smem_ptr);
    asm volatile("cp.async.cg.shared.global [%0], [%1], 16;\n" ::"r"(s), "l"(gmem_ptr));
}
__device__ __forceinline__ void cp_commit() { asm volatile("cp.async.commit_group;\n"); }
template <int N>
__device__ __forceinline__ void cp_wait() {
    asm volatile("cp.async.wait_group %0;\n" ::"n"(N));
}
__device__ __forceinline__ float silu(float x) { return x / (1.f + __expf(-x)); }

__global__ void f2h(const float4* __restrict__ src, uint2* __restrict__ dst, size_t n4) {
    size_t i = (size_t)blockIdx.x * blockDim.x + threadIdx.x;
    const size_t stride = (size_t)gridDim.x * blockDim.x;
    for (; i < n4; i += stride) {
        float4 v = src[i];
        __half2 h0 = __floats2half2_rn(v.x, v.y);
        __half2 h1 = __floats2half2_rn(v.z, v.w);
        dst[i] = make_uint2(*reinterpret_cast<uint32_t*>(&h0), *reinterpret_cast<uint32_t*>(&h1));
    }
}

// C[e,m,n] = sum_k A[e,m,k]*B[e,n,k]; fp16 in, fp32 acc. (e = blockIdx.z)
// MODE 0: raw acc -> __half*; MODE 1: silu(Gpre)*acc -> __half*; MODE 2: raw acc -> float*
template <int MODE>
__global__ void __launch_bounds__(THREADS, 3)
gemm_nt(const __half* __restrict__ A, const __half* __restrict__ B,
        const __half* __restrict__ Gpre, void* __restrict__ CoutV,
        int N, int K, long strideA, long strideB, long strideC) {
    extern __shared__ __half smh[];
    const uint32_t smbase = (uint32_t)__cvta_generic_to_shared(smh);

    const int e = blockIdx.z;
    const __half* Ae = A + (long)e * strideA;
    const __half* Be = B + (long)e * strideB;

    const int bm = blockIdx.y, bn = blockIdx.x;
    const int tid = threadIdx.x;
    const int warp = tid >> 5, lane = tid & 31;
    const int wm = warp >> 1, wn = warp & 1;
    const int gid = lane >> 2, tig = lane & 3;

    const uint32_t aoff = ((uint32_t)(((lane & 7) + ((lane >> 3) & 1) * 8) * LDSH +
                                      ((lane >> 4) & 1) * 8)) * 2;
    const uint32_t boff = ((uint32_t)(((lane & 7) + ((lane >> 4) & 1) * 8) * LDSH +
                                      ((lane >> 3) & 1) * 8)) * 2;

    const int lrow = tid >> 2;
    const int lch = (tid & 3) * 8;

    const __half* Ag = Ae + (long)(bm * BM + lrow) * K + lch;
    const __half* Bg = Be + (long)(bn * BN + lrow) * K + lch;

    float acc[4][8][4];
#pragma unroll
    for (int mt = 0; mt < 4; mt++)
#pragma unroll
        for (int nt = 0; nt < 8; nt++)
#pragma unroll
            for (int r = 0; r < 4; r++) acc[mt][nt][r] = 0.f;

    const int KT = K / BK;

    auto load_stage = [&](int kt) {
        __half* as = smh + (kt & 1) * STAGE_H;
        __half* bs = as + BM * LDSH;
        const long ko = (long)kt * BK;
#pragma unroll
        for (int i = 0; i < 4; i++) {
            cp_async16(&as[(lrow + i * 32) * LDSH + lch], Ag + (long)(i * 32) * K + ko);
            cp_async16(&bs[(lrow + i * 32) * LDSH + lch], Bg + (long)(i * 32) * K + ko);
        }
    };

    load_stage(0); cp_commit();

    for (int kt = 0; kt < KT; ++kt) {
        if (kt + 1 < KT) load_stage(kt + 1);   // prefetch before wait (R6 ordering)
        cp_commit();
        cp_wait<1>();
        __syncthreads();

        const uint32_t as_u = smbase + (uint32_t)((kt & 1) * STAGE_H * 2);
        const uint32_t abase = as_u + (uint32_t)(wm * 64 * LDSH * 2) + aoff;
        const uint32_t bbase = as_u + (uint32_t)(BM * LDSH * 2) + (uint32_t)(wn * 64 * LDSH * 2) + boff;

#pragma unroll
        for (int k16 = 0; k16 < BK / 16; k16++) {
            const uint32_t kcb = (uint32_t)(k16 * 32);
            uint32_t afr[4][4];
            uint32_t bfr[4][4];
#pragma unroll
            for (int mt = 0; mt < 4; mt++)
                ldsm_x4(afr[mt], abase + (uint32_t)(mt * 16 * LDSH * 2) + kcb);
#pragma unroll
            for (int p = 0; p < 4; p++)
                ldsm_x4(bfr[p], bbase + (uint32_t)(p * 16 * LDSH * 2) + kcb);
#pragma unroll
            for (int mt = 0; mt < 4; mt++)
#pragma unroll
                for (int nt = 0; nt < 8; nt++)
                    mma_f16(acc[mt][nt], afr[mt], bfr[nt >> 1][(nt & 1) * 2],
                            bfr[nt >> 1][(nt & 1) * 2 + 1]);
        }
        __syncthreads();
    }

    const long base = (long)e * strideC;
#pragma unroll
    for (int mt = 0; mt < 4; mt++) {
#pragma unroll
        for (int nt = 0; nt < 8; nt++) {
            const int row0 = bm * BM + wm * 64 + mt * 16 + gid;
            const int col = bn * BN + wn * 64 + nt * 8 + tig * 2;
            const long i0 = base + (long)row0 * N + col;
            const long i1 = base + (long)(row0 + 8) * N + col;
            if (MODE == 0) {
                __half* Cout = (__half*)CoutV;
                *reinterpret_cast<__half2*>(Cout + i0) =
                    __floats2half2_rn(acc[mt][nt][0], acc[mt][nt][1]);
                *reinterpret_cast<__half2*>(Cout + i1) =
                    __floats2half2_rn(acc[mt][nt][2], acc[mt][nt][3]);
            } else if (MODE == 1) {
                __half* Cout = (__half*)CoutV;
                const float2 g0 = __half22float2(*reinterpret_cast<const __half2*>(Gpre + i0));
                const float2 g1 = __half22float2(*reinterpret_cast<const __half2*>(Gpre + i1));
                *reinterpret_cast<__half2*>(Cout + i0) =
                    __floats2half2_rn(silu(g0.x) * acc[mt][nt][0], silu(g0.y) * acc[mt][nt][1]);
                *reinterpret_cast<__half2*>(Cout + i1) =
                    __floats2half2_rn(silu(g1.x) * acc[mt][nt][2], silu(g1.y) * acc[mt][nt][3]);
            } else {
                float* Cout = (float*)CoutV;
                *reinterpret_cast<float2*>(Cout + i0) = make_float2(acc[mt][nt][0], acc[mt][nt][1]);
                *reinterpret_cast<float2*>(Cout + i1) = make_float2(acc[mt][nt][2], acc[mt][nt][3]);
            }
        }
    }
}

extern "C" void kernel_launch(void* const* d_in, const int* in_sizes, int n_in,
                              void* d_out, int out_size) {
    const float* x    = (const float*)d_in[0];
    const float* gate = (const float*)d_in[1];
    const float* up   = (const float*)d_in[2];
    const float* down = (const float*)d_in[3];
    float* out = (float*)d_out;

    __half *px16, *pg16, *pu16, *pd16, *pi16, *pgh;
    cudaGetSymbolAddress((void**)&px16, x16);
    cudaGetSymbolAddress((void**)&pg16, g16);
    cudaGetSymbolAddress((void**)&pu16, u16);
    cudaGetSymbolAddress((void**)&pd16, d16);
    cudaGetSymbolAddress((void**)&pi16, inter16);
    cudaGetSymbolAddress((void**)&pgh, gateh);

    cudaFuncSetAttribute(gemm_nt<0>, cudaFuncAttributeMaxDynamicSharedMemorySize, SMEM_BYTES);
    cudaFuncSetAttribute(gemm_nt<1>, cudaFuncAttributeMaxDynamicSharedMemorySize, SMEM_BYTES);
    cudaFuncSetAttribute(gemm_nt<2>, cudaFuncAttributeMaxDynamicSharedMemorySize, SMEM_BYTES);

    static cudaStream_t s2 = nullptr, s3 = nullptr;
    static cudaEvent_t ev_gA = nullptr, ev_gB = nullptr, ev_up = nullptr,
                       ev_down = nullptr, ev_g0B = nullptr, ev_join = nullptr;
    if (!s2) {
        cudaStreamCreateWithFlags(&s2, cudaStreamNonBlocking);
        cudaStreamCreateWithFlags(&s3, cudaStreamNonBlocking);
        cudaEventCreateWithFlags(&ev_gA, cudaEventDisableTiming);
        cudaEventCreateWithFlags(&ev_gB, cudaEventDisableTiming);
        cudaEventCreateWithFlags(&ev_up, cudaEventDisableTiming);
        cudaEventCreateWithFlags(&ev_down, cudaEventDisableTiming);
        cudaEventCreateWithFlags(&ev_g0B, cudaEventDisableTiming);
        cudaEventCreateWithFlags(&ev_join, cudaEventDisableTiming);
    }

    const size_t nX = (size_t)E_ * C_ * H_, nW = (size_t)E_ * I_ * H_, nD = (size_t)E_ * H_ * I_;
    const size_t nWh = nW / 2;                   // half the gate tensor (4 experts)
    const long sA0 = (long)C_ * H_, sB0 = (long)I_ * H_, sC0 = (long)C_ * I_;

    // conversion queue (capture stream 0): x, gate in 2 full-bandwidth halves, up, down
    f2h<<<1024, 256>>>((const float4*)x, (uint2*)px16, nX / 4);
    f2h<<<1024, 256>>>((const float4*)gate, (uint2*)pg16, nWh / 4);
    cudaEventRecord(ev_gA, 0);
    f2h<<<1024, 256>>>((const float4*)(gate + nWh), (uint2*)(pg16 + nWh), nWh / 4);
    cudaEventRecord(ev_gB, 0);
    f2h<<<2048, 256>>>((const float4*)up, (uint2*)pu16, nW / 4);
    cudaEventRecord(ev_up, 0);
    f2h<<<2048, 256>>>((const float4*)down, (uint2*)pd16, nD / 4);
    cudaEventRecord(ev_down, 0);

    dim3 blk(THREADS);

    // gemm0 chunk A (experts 0-3) on s2; chunk B (experts 4-7) on s3 (fills A's tail)
    cudaStreamWaitEvent(s2, ev_gA, 0);
    gemm_nt<0><<<dim3(I_ / BN, C_ / BM, 4), blk, SMEM_BYTES, s2>>>(
        px16, pg16, nullptr, pgh, I_, H_, sA0, sB0, sC0);

    cudaStreamWaitEvent(s3, ev_gB, 0);
    gemm_nt<0><<<dim3(I_ / BN, C_ / BM, 4), blk, SMEM_BYTES, s3>>>(
        px16 + 4 * (size_t)sA0, pg16 + 4 * (size_t)sB0, nullptr,
        pgh + 4 * (size_t)sC0, I_, H_, sA0, sB0, sC0);
    cudaEventRecord(ev_g0B, s3);

    // gemm1 on s2: needs up + both gemm0 chunks (chunk A is s2-ordered already)
    cudaStreamWaitEvent(s2, ev_up, 0);
    cudaStreamWaitEvent(s2, ev_g0B, 0);
    gemm_nt<1><<<dim3(I_ / BN, C_ / BM, E_), blk, SMEM_BYTES, s2>>>(
        px16, pu16, pgh, pi16, I_, H_, sA0, sB0, sC0);

    cudaStreamWaitEvent(s2, ev_down, 0);
    gemm_nt<2><<<dim3(H_ / BN, C_ / BM, E_), blk, SMEM_BYTES, s2>>>(
        pi16, pd16, nullptr, out, H_, I_,
        (long)C_ * I_, (long)H_ * I_, (long)C_ * H_);

    cudaEventRecord(ev_join, s2);
    cudaStreamWaitEvent(0, ev_join, 0);
}